// round 1
// baseline (speedup 1.0000x reference)
#include <cuda_runtime.h>
#include <math.h>

// Problem constants
#define Bb 2
#define Ll 2048
#define Dd 2048
#define Ee 4096
#define Nn 16
#define Rr 128
#define Kk 4
#define Mm (Bb*Ll)      // 4096 tokens
#define SPLITK 8

// ---------------- scratch (device globals: no allocations allowed) ------------
__device__ float g_xn[Mm*Dd];          // RMSNorm output
__device__ float g_skip[Mm*Ee];        // skip = xn @ W_skip^T
__device__ float g_xin[Mm*Ee];         // xn @ W_in^T (conv input)
__device__ float g_xs[Mm*Ee];          // silu(conv(...)) : ssm input
__device__ float g_BC[Mm*128];         // cols 0..15 = Bt, 16..31 = Ct (rest garbage-free zeros)
__device__ float g_d1[Mm*Rr];          // xs @ W_d1^T
__device__ float g_part[SPLITK*Mm*128];// split-K partials
__device__ float g_delta[Mm*Ee];       // softplus(d1 @ W_d2^T + b)
__device__ float g_y[Mm*Ee];           // scan output (already gated)
__device__ float g_Wbc[128*Ee];        // packed [W_Bm;W_Cm;zeros] weight, rows 32..127 stay 0

// ---------------- RMSNorm ------------------------------------------------------
__global__ void rmsnorm_kernel(const float* __restrict__ resid,
                               const float* __restrict__ w) {
    const int row = blockIdx.x;                 // 0..Mm-1
    const int t = threadIdx.x;                  // 256 threads
    const float4* in = reinterpret_cast<const float4*>(resid + (size_t)row * Dd);
    float4* out = reinterpret_cast<float4*>(g_xn + (size_t)row * Dd);
    float4 v0 = in[t];
    float4 v1 = in[t + 256];
    float ss = v0.x*v0.x + v0.y*v0.y + v0.z*v0.z + v0.w*v0.w
             + v1.x*v1.x + v1.y*v1.y + v1.z*v1.z + v1.w*v1.w;
    // block reduce
    #pragma unroll
    for (int o = 16; o > 0; o >>= 1) ss += __shfl_xor_sync(0xffffffffu, ss, o);
    __shared__ float red[8];
    if ((t & 31) == 0) red[t >> 5] = ss;
    __syncthreads();
    float tot = red[0] + red[1] + red[2] + red[3] + red[4] + red[5] + red[6] + red[7];
    float scale = rsqrtf(tot * (1.0f / Dd) + 1e-5f);
    const float4* wv = reinterpret_cast<const float4*>(w);
    float4 w0 = wv[t], w1 = wv[t + 256];
    out[t]       = make_float4(v0.x*scale*w0.x, v0.y*scale*w0.y, v0.z*scale*w0.z, v0.w*scale*w0.w);
    out[t + 256] = make_float4(v1.x*scale*w1.x, v1.y*scale*w1.y, v1.z*scale*w1.z, v1.w*scale*w1.w);
}

// ---------------- generic tiled SGEMM: C[M,N] = A[M,K] @ B[N,K]^T ---------------
// epi: 0 = plain store, 1 = softplus(x + bias[n]), 2 = x + addend[m*N+n]
// if gridDim.z > 1 : deterministic split-K, partial z written at C + z*M*N, epi ignored(=0)
__global__ __launch_bounds__(256)
void sgemm_kernel(const float* __restrict__ A, const float* __restrict__ Bw,
                  float* __restrict__ C, int M, int N, int K, int kChunk,
                  int epi, const float* __restrict__ bias,
                  const float* __restrict__ addend) {
    __shared__ float As[8][128];
    __shared__ float Bs[8][128];
    const int bx = blockIdx.x, by = blockIdx.y, bz = blockIdx.z;
    const int row0 = by * 128, col0 = bx * 128;
    const int k0 = bz * kChunk;
    const int tid = threadIdx.x;
    const int lr = tid >> 1;            // tile row for loading (0..127)
    const int lc = (tid & 1) * 4;       // 0 or 4 (float4 column)
    const float* Ap = A + (size_t)(row0 + lr) * K + k0 + lc;
    const float* Bp = Bw + (size_t)(col0 + lr) * K + k0 + lc;
    const int tx = tid & 15, ty = tid >> 4;
    float acc[8][8];
    #pragma unroll
    for (int i = 0; i < 8; i++)
        #pragma unroll
        for (int j = 0; j < 8; j++) acc[i][j] = 0.f;

    const int ktiles = kChunk / 8;
    for (int t = 0; t < ktiles; ++t) {
        float4 av = *reinterpret_cast<const float4*>(Ap + t * 8);
        float4 bv = *reinterpret_cast<const float4*>(Bp + t * 8);
        __syncthreads();
        As[lc + 0][lr] = av.x; As[lc + 1][lr] = av.y;
        As[lc + 2][lr] = av.z; As[lc + 3][lr] = av.w;
        Bs[lc + 0][lr] = bv.x; Bs[lc + 1][lr] = bv.y;
        Bs[lc + 2][lr] = bv.z; Bs[lc + 3][lr] = bv.w;
        __syncthreads();
        #pragma unroll
        for (int k = 0; k < 8; k++) {
            float4 a0 = *reinterpret_cast<const float4*>(&As[k][ty * 8]);
            float4 a1 = *reinterpret_cast<const float4*>(&As[k][ty * 8 + 4]);
            float4 b0 = *reinterpret_cast<const float4*>(&Bs[k][tx * 8]);
            float4 b1 = *reinterpret_cast<const float4*>(&Bs[k][tx * 8 + 4]);
            float av8[8] = {a0.x, a0.y, a0.z, a0.w, a1.x, a1.y, a1.z, a1.w};
            float bv8[8] = {b0.x, b0.y, b0.z, b0.w, b1.x, b1.y, b1.z, b1.w};
            #pragma unroll
            for (int i = 0; i < 8; i++)
                #pragma unroll
                for (int j = 0; j < 8; j++)
                    acc[i][j] = fmaf(av8[i], bv8[j], acc[i][j]);
        }
    }

    float* Cb = C;
    if (gridDim.z > 1) Cb = C + (size_t)bz * M * N;
    #pragma unroll
    for (int i = 0; i < 8; i++) {
        int row = row0 + ty * 8 + i;
        float* cr = Cb + (size_t)row * N + col0 + tx * 8;
        float v[8];
        if (epi == 1) {
            #pragma unroll
            for (int j = 0; j < 8; j++) {
                float z = acc[i][j] + bias[col0 + tx * 8 + j];
                v[j] = (z > 20.f) ? z : log1pf(expf(z));
            }
        } else if (epi == 2) {
            #pragma unroll
            for (int j = 0; j < 8; j++) v[j] = acc[i][j] + addend[(size_t)row * N + col0 + tx * 8 + j];
        } else {
            #pragma unroll
            for (int j = 0; j < 8; j++) v[j] = acc[i][j];
        }
        *reinterpret_cast<float4*>(cr)     = make_float4(v[0], v[1], v[2], v[3]);
        *reinterpret_cast<float4*>(cr + 4) = make_float4(v[4], v[5], v[6], v[7]);
    }
}

// ---------------- split-K reduce -----------------------------------------------
__global__ void reduce_split_kernel(const float* __restrict__ p, float* __restrict__ o, int n) {
    int i = blockIdx.x * blockDim.x + threadIdx.x;
    if (i >= n) return;
    float s = 0.f;
    #pragma unroll
    for (int z = 0; z < SPLITK; z++) s += p[i + (size_t)z * n];
    o[i] = s;
}

// ---------------- depthwise causal conv(K=4) + SiLU -----------------------------
__global__ void conv_silu_kernel(const float* __restrict__ cw, const float* __restrict__ cb) {
    int idx = blockIdx.x * blockDim.x + threadIdx.x;   // < Mm*Ee
    int e = idx & (Ee - 1);
    int l = (idx >> 12) & (Ll - 1);                    // Ee = 4096 = 2^12
    float w0 = cw[e * 4 + 0], w1 = cw[e * 4 + 1], w2 = cw[e * 4 + 2], w3 = cw[e * 4 + 3];
    const float* xp = g_xin + idx;
    float acc = cb[e] + w3 * xp[0];
    if (l >= 1) acc += w2 * xp[-Ee];
    if (l >= 2) acc += w1 * xp[-2 * Ee];
    if (l >= 3) acc += w0 * xp[-3 * Ee];
    g_xs[idx] = acc / (1.f + __expf(-acc));
}

// ---------------- pack W_Bm / W_Cm into padded 128-row weight -------------------
__global__ void pack_wbc_kernel(const float* __restrict__ wb, const float* __restrict__ wc) {
    int i = blockIdx.x * blockDim.x + threadIdx.x;     // < 32*Ee
    int row = i >> 12;
    int k = i & (Ee - 1);
    g_Wbc[i] = (row < 16) ? wb[row * Ee + k] : wc[(row - 16) * Ee + k];
}

// ---------------- selective scan -------------------------------------------------
// thread = (channel, n); half-warp (16 lanes) owns one (b,e) channel
__global__ __launch_bounds__(128)
void scan_kernel(const float* __restrict__ A_log, const float* __restrict__ W_D) {
    const int tid = threadIdx.x;
    const int half = tid >> 4;
    const int n = tid & 15;
    const int ch = blockIdx.x * 8 + half;   // 0..Bb*Ee-1
    const int b = ch >> 12;                 // Ee = 4096
    const int e = ch & (Ee - 1);
    const float An = -__expf(A_log[e * Nn + n]);
    const float wD = W_D[e];
    float h = 0.f;
    int base = (b * Ll) * Ee + e;
    int bcb = (b * Ll) * 128 + n;
    for (int l = 0; l < Ll; ++l) {
        float d  = g_delta[base];
        float xv = g_xs[base];
        float bv = g_BC[bcb];
        float cv = g_BC[bcb + 16];
        float a = __expf(d * An);
        h = fmaf(a, h, d * xv * bv);
        float p = h * cv;
        p += __shfl_xor_sync(0xffffffffu, p, 8);
        p += __shfl_xor_sync(0xffffffffu, p, 4);
        p += __shfl_xor_sync(0xffffffffu, p, 2);
        p += __shfl_xor_sync(0xffffffffu, p, 1);
        if (n == 0) {
            float sk = g_skip[base];
            float sg = sk / (1.f + __expf(-sk));     // silu(skip)
            g_y[base] = (p + xv * wD) * sg;
        }
        base += Ee;
        bcb += 128;
    }
}

// ---------------- host orchestration --------------------------------------------
extern "C" void kernel_launch(void* const* d_in, const int* in_sizes, int n_in,
                              void* d_out, int out_size) {
    const float* resid  = (const float*)d_in[0];
    const float* norm_w = (const float*)d_in[1];
    const float* W_skip = (const float*)d_in[2];
    const float* W_in   = (const float*)d_in[3];
    const float* conv_w = (const float*)d_in[4];
    const float* conv_b = (const float*)d_in[5];
    const float* W_d1   = (const float*)d_in[6];
    const float* W_d2   = (const float*)d_in[7];
    const float* b_d2   = (const float*)d_in[8];
    const float* W_Bm   = (const float*)d_in[9];
    const float* W_Cm   = (const float*)d_in[10];
    const float* A_log  = (const float*)d_in[11];
    const float* W_D    = (const float*)d_in[12];
    const float* W_out  = (const float*)d_in[13];
    float* out = (float*)d_out;

    float *p_xn, *p_skip, *p_xin, *p_xs, *p_BC, *p_d1, *p_part, *p_delta, *p_y, *p_Wbc;
    cudaGetSymbolAddress((void**)&p_xn, g_xn);
    cudaGetSymbolAddress((void**)&p_skip, g_skip);
    cudaGetSymbolAddress((void**)&p_xin, g_xin);
    cudaGetSymbolAddress((void**)&p_xs, g_xs);
    cudaGetSymbolAddress((void**)&p_BC, g_BC);
    cudaGetSymbolAddress((void**)&p_d1, g_d1);
    cudaGetSymbolAddress((void**)&p_part, g_part);
    cudaGetSymbolAddress((void**)&p_delta, g_delta);
    cudaGetSymbolAddress((void**)&p_y, g_y);
    cudaGetSymbolAddress((void**)&p_Wbc, g_Wbc);

    // 1. RMSNorm
    rmsnorm_kernel<<<Mm, 256>>>(resid, norm_w);

    // 2. skip = xn @ W_skip^T   [4096 x 4096], K=2048
    sgemm_kernel<<<dim3(Ee / 128, Mm / 128, 1), 256>>>(
        p_xn, W_skip, p_skip, Mm, Ee, Dd, Dd, 0, nullptr, nullptr);
    // 3. xin = xn @ W_in^T
    sgemm_kernel<<<dim3(Ee / 128, Mm / 128, 1), 256>>>(
        p_xn, W_in, p_xin, Mm, Ee, Dd, Dd, 0, nullptr, nullptr);

    // 4. depthwise conv + silu -> xs
    conv_silu_kernel<<<(Mm * Ee) / 256, 256>>>(conv_w, conv_b);

    // 5. pack [W_Bm; W_Cm] into 128-row padded weight
    pack_wbc_kernel<<<(32 * Ee) / 256, 256>>>(W_Bm, W_Cm);

    // 6. BC = xs @ Wbc^T  [4096 x 128], K=4096, split-K=8 (deterministic)
    sgemm_kernel<<<dim3(1, Mm / 128, SPLITK), 256>>>(
        p_xs, p_Wbc, p_part, Mm, 128, Ee, Ee / SPLITK, 0, nullptr, nullptr);
    reduce_split_kernel<<<(Mm * 128) / 256, 256>>>(p_part, p_BC, Mm * 128);

    // 7. d1 = xs @ W_d1^T  [4096 x 128], K=4096, split-K=8
    sgemm_kernel<<<dim3(1, Mm / 128, SPLITK), 256>>>(
        p_xs, W_d1, p_part, Mm, Rr, Ee, Ee / SPLITK, 0, nullptr, nullptr);
    reduce_split_kernel<<<(Mm * Rr) / 256, 256>>>(p_part, p_d1, Mm * Rr);

    // 8. delta = softplus(d1 @ W_d2^T + b_d2)  [4096 x 4096], K=128
    sgemm_kernel<<<dim3(Ee / 128, Mm / 128, 1), 256>>>(
        p_d1, W_d2, p_delta, Mm, Ee, Rr, Rr, 1, b_d2, nullptr);

    // 9. selective scan (fuses + x*W_D and * silu(skip)) -> y
    scan_kernel<<<(Bb * Ee) / 8, 128>>>(A_log, W_D);

    // 10. out = resid + y @ W_out^T   [4096 x 2048], K=4096
    sgemm_kernel<<<dim3(Dd / 128, Mm / 128, 1), 256>>>(
        p_y, W_out, out, Mm, Dd, Ee, Ee, 2, nullptr, resid);

    (void)in_sizes; (void)n_in; (void)out_size;
}

// round 3
// speedup vs baseline: 1.6822x; 1.6822x over previous
#include <cuda_runtime.h>
#include <cuda_fp16.h>
#include <math.h>
#include <stdint.h>

// Problem constants
#define Bb 2
#define Ll 2048
#define Dd 2048
#define Ee 4096
#define Nn 16
#define Rr 128
#define Mm (Bb*Ll)      // 4096 tokens

// ---------------- fp32 scratch ---------------------------------------------------
__device__ float g_skip[Mm*Ee];
__device__ float g_xin[Mm*Ee];
__device__ float g_xs[Mm*Ee];
__device__ float g_BC[Mm*128];
__device__ float g_part[4*Mm*128];
__device__ float g_delta[Mm*Ee];

// ---------------- fp16 hi/lo scratch ---------------------------------------------
__device__ __half g_xnh[Mm*Dd],  g_xnl[Mm*Dd];
__device__ __half g_xsh[Mm*Ee],  g_xsl[Mm*Ee];
__device__ __half g_yh[Mm*Ee],   g_yl[Mm*Ee];
__device__ __half g_d1h[Mm*Rr],  g_d1l[Mm*Rr];
__device__ __half g_wskiph[Ee*Dd], g_wskipl[Ee*Dd];
__device__ __half g_winh[Ee*Dd],   g_winl[Ee*Dd];
__device__ __half g_wouth[Dd*Ee],  g_woutl[Dd*Ee];
__device__ __half g_wbch[128*Ee],  g_wbcl[128*Ee];
__device__ __half g_wd1h[Rr*Ee],   g_wd1l[Rr*Ee];
__device__ __half g_wd2h[Ee*Rr],   g_wd2l[Ee*Rr];

// =============================== PTX helpers ====================================
__device__ __forceinline__ uint32_t smem_u32(const void* p) {
    uint32_t a;
    asm("{ .reg .u64 t; cvta.to.shared.u64 t, %1; cvt.u32.u64 %0, t; }" : "=r"(a) : "l"(p));
    return a;
}
__device__ __forceinline__ void cp16(uint32_t s, const void* g) {
    uint64_t ga;
    asm("cvta.to.global.u64 %0, %1;" : "=l"(ga) : "l"(g));
    asm volatile("cp.async.cg.shared.global [%0], [%1], 16;" :: "r"(s), "l"(ga) : "memory");
}
#define CP_COMMIT() asm volatile("cp.async.commit_group;" ::: "memory")
#define CP_WAIT1()  asm volatile("cp.async.wait_group 1;" ::: "memory")
#define CP_WAIT0()  asm volatile("cp.async.wait_group 0;" ::: "memory")
#define LDSM4(r, addr) \
    asm volatile("ldmatrix.sync.aligned.m8n8.x4.shared.b16 {%0,%1,%2,%3}, [%4];" \
        : "=r"((r)[0]), "=r"((r)[1]), "=r"((r)[2]), "=r"((r)[3]) : "r"(addr))
#define MMA16816(d, a, b0, b1) \
    asm volatile("mma.sync.aligned.m16n8k16.row.col.f32.f16.f16.f32 " \
        "{%0,%1,%2,%3}, {%4,%5,%6,%7}, {%8,%9}, {%0,%1,%2,%3};" \
        : "+f"((d)[0]), "+f"((d)[1]), "+f"((d)[2]), "+f"((d)[3]) \
        : "r"((a)[0]), "r"((a)[1]), "r"((a)[2]), "r"((a)[3]), "r"(b0), "r"(b1))

// SMEM: per stage: Ah(8KB) Al(8KB) Bh(8KB) Bl(8KB) = 32KB. 3 stages.
#define STAGES   3
#define STAGE_B  32768
#define SMEM_DYN (STAGES * STAGE_B)

// swizzled byte offset inside one 128x32-half tile (row stride 64B, 16B chunks)
__device__ __forceinline__ uint32_t swz(uint32_t row, uint32_t chunk) {
    return row * 64u + ((chunk ^ ((row >> 1) & 3u)) * 16u);
}

// ======================= HMMA GEMM (fp16 x 3 compensated) =======================
// C[M,N] = A[M,K] @ B[N,K]^T with A=Ah+Al, B=Bh+Bl (fp16 hi/lo pairs).
// 128x128 CTA tile, 256 threads (8 warps: 4 along M x 2 along N, warp tile 32x64).
// epi: 0=plain (split-K partial if gridDim.z>1), 1=softplus(x+bias[n]), 2=x+addend
__global__ __launch_bounds__(256, 1)
void gemm_hmma(const __half* __restrict__ Ah, const __half* __restrict__ Al,
               const __half* __restrict__ Bh, const __half* __restrict__ Bl,
               float* __restrict__ C, int M, int N, int K, int kChunk,
               int epi, const float* __restrict__ bias,
               const float* __restrict__ addend) {
    extern __shared__ char dsm[];
    const uint32_t sb = smem_u32(dsm);
    const int tid = threadIdx.x, wid = tid >> 5, lane = tid & 31;
    const int m0 = blockIdx.y * 128, n0 = blockIdx.x * 128;
    const int k0 = blockIdx.z * kChunk;
    const int C_CH = kChunk / 32;
    const int m0w = (wid & 3) * 32, n0w = (wid >> 2) * 64;

    const __half* Abh = Ah + (size_t)m0 * K + k0;
    const __half* Abl = Al + (size_t)m0 * K + k0;
    const __half* Bbh = Bh + (size_t)n0 * K + k0;
    const __half* Bbl = Bl + (size_t)n0 * K + k0;

    // loader mapping: thread -> row, chunk pair
    const int lrow = tid >> 1;
    const int lcp  = (tid & 1) * 2;

    // prologue loads
    for (int s = 0; s < STAGES - 1; s++) {
        if (s < C_CH) {
            uint32_t tb = sb + s * STAGE_B;
            size_t go = (size_t)lrow * K + (size_t)s * 32;
            #pragma unroll
            for (int cc = 0; cc < 2; cc++) {
                int c = lcp + cc;
                uint32_t so = swz(lrow, c);
                cp16(tb + so,          Abh + go + c * 8);
                cp16(tb + 8192 + so,   Abl + go + c * 8);
                cp16(tb + 16384 + so,  Bbh + go + c * 8);
                cp16(tb + 24576 + so,  Bbl + go + c * 8);
            }
        }
        CP_COMMIT();
    }

    float acc[2][8][4];
    #pragma unroll
    for (int i = 0; i < 2; i++)
        #pragma unroll
        for (int j = 0; j < 8; j++)
            #pragma unroll
            for (int q = 0; q < 4; q++) acc[i][j][q] = 0.f;

    const int chi = lane >> 4;           // ldmatrix half-select
    const int lr15 = lane & 15;

    for (int t = 0; t < C_CH; t++) {
        if (t + STAGES - 1 < C_CH) { CP_WAIT1(); } else { CP_WAIT0(); }
        __syncthreads();
        // issue loads for chunk t+2
        if (t + STAGES - 1 < C_CH) {
            int tc = t + STAGES - 1;
            uint32_t tb = sb + (tc % STAGES) * STAGE_B;
            size_t go = (size_t)lrow * K + (size_t)tc * 32;
            #pragma unroll
            for (int cc = 0; cc < 2; cc++) {
                int c = lcp + cc;
                uint32_t so = swz(lrow, c);
                cp16(tb + so,          Abh + go + c * 8);
                cp16(tb + 8192 + so,   Abl + go + c * 8);
                cp16(tb + 16384 + so,  Bbh + go + c * 8);
                cp16(tb + 24576 + so,  Bbl + go + c * 8);
            }
        }
        CP_COMMIT();

        // compute chunk t
        uint32_t tb = sb + (t % STAGES) * STAGE_B;
        #pragma unroll
        for (int ks = 0; ks < 2; ks++) {
            uint32_t ah[2][4], al[2][4], bh[4][4], bl[4][4];
            const uint32_t c = (uint32_t)(ks * 2 + chi);
            #pragma unroll
            for (int mi = 0; mi < 2; mi++) {
                uint32_t r = (uint32_t)(m0w + mi * 16 + lr15);
                uint32_t ad = tb + swz(r, c);
                LDSM4(ah[mi], ad);
                LDSM4(al[mi], ad + 8192);
            }
            #pragma unroll
            for (int nj = 0; nj < 4; nj++) {
                uint32_t r = (uint32_t)(n0w + nj * 16 + lr15);
                uint32_t ad = tb + 16384 + swz(r, c);
                LDSM4(bh[nj], ad);
                LDSM4(bl[nj], ad + 8192);
            }
            #pragma unroll
            for (int mi = 0; mi < 2; mi++)
                #pragma unroll
                for (int nj = 0; nj < 4; nj++) {
                    MMA16816(acc[mi][nj*2+0], ah[mi], bh[nj][0], bh[nj][2]);
                    MMA16816(acc[mi][nj*2+1], ah[mi], bh[nj][1], bh[nj][3]);
                    MMA16816(acc[mi][nj*2+0], ah[mi], bl[nj][0], bl[nj][2]);
                    MMA16816(acc[mi][nj*2+1], ah[mi], bl[nj][1], bl[nj][3]);
                    MMA16816(acc[mi][nj*2+0], al[mi], bh[nj][0], bh[nj][2]);
                    MMA16816(acc[mi][nj*2+1], al[mi], bh[nj][1], bh[nj][3]);
                }
        }
    }

    // epilogue
    float* Cb = C + (gridDim.z > 1 ? (size_t)blockIdx.z * M * N : 0);
    const int gid = lane >> 2, tig = lane & 3;
    #pragma unroll
    for (int mi = 0; mi < 2; mi++) {
        #pragma unroll
        for (int nb = 0; nb < 8; nb++) {
            int col = n0 + n0w + (nb >> 1) * 16 + (nb & 1) * 8 + tig * 2;
            int row = m0 + m0w + mi * 16 + gid;
            float v[4] = {acc[mi][nb][0], acc[mi][nb][1], acc[mi][nb][2], acc[mi][nb][3]};
            if (epi == 1) {
                float z0 = v[0] + bias[col],     z1 = v[1] + bias[col + 1];
                float z2 = v[2] + bias[col],     z3 = v[3] + bias[col + 1];
                v[0] = (z0 > 20.f) ? z0 : log1pf(expf(z0));
                v[1] = (z1 > 20.f) ? z1 : log1pf(expf(z1));
                v[2] = (z2 > 20.f) ? z2 : log1pf(expf(z2));
                v[3] = (z3 > 20.f) ? z3 : log1pf(expf(z3));
            } else if (epi == 2) {
                v[0] += addend[(size_t)row * N + col];
                v[1] += addend[(size_t)row * N + col + 1];
                v[2] += addend[(size_t)(row + 8) * N + col];
                v[3] += addend[(size_t)(row + 8) * N + col + 1];
            }
            *reinterpret_cast<float2*>(Cb + (size_t)row * N + col)       = make_float2(v[0], v[1]);
            *reinterpret_cast<float2*>(Cb + (size_t)(row + 8) * N + col) = make_float2(v[2], v[3]);
        }
    }
}

// ---------------- fp32 -> fp16 hi/lo convert ------------------------------------
__global__ void cvt_pair_kernel(const float* __restrict__ in,
                                __half* __restrict__ h, __half* __restrict__ l, int n) {
    int i = blockIdx.x * 256 + threadIdx.x;
    if (i >= n) return;
    float v = in[i];
    __half hh = __float2half_rn(v);
    h[i] = hh;
    l[i] = __float2half_rn(v - __half2float(hh));
}

// ---------------- RMSNorm (writes fp16 hi/lo) ------------------------------------
__global__ void rmsnorm_kernel(const float* __restrict__ resid,
                               const float* __restrict__ w) {
    const int row = blockIdx.x;
    const int t = threadIdx.x;
    const float4* in = reinterpret_cast<const float4*>(resid + (size_t)row * Dd);
    float4 v0 = in[t];
    float4 v1 = in[t + 256];
    float ss = v0.x*v0.x + v0.y*v0.y + v0.z*v0.z + v0.w*v0.w
             + v1.x*v1.x + v1.y*v1.y + v1.z*v1.z + v1.w*v1.w;
    #pragma unroll
    for (int o = 16; o > 0; o >>= 1) ss += __shfl_xor_sync(0xffffffffu, ss, o);
    __shared__ float red[8];
    if ((t & 31) == 0) red[t >> 5] = ss;
    __syncthreads();
    float tot = red[0] + red[1] + red[2] + red[3] + red[4] + red[5] + red[6] + red[7];
    float scale = rsqrtf(tot * (1.0f / Dd) + 1e-5f);
    const float4* wv = reinterpret_cast<const float4*>(w);
    float4 w0 = wv[t], w1 = wv[t + 256];
    __half2* oh = reinterpret_cast<__half2*>(g_xnh + (size_t)row * Dd);
    __half2* ol = reinterpret_cast<__half2*>(g_xnl + (size_t)row * Dd);
    float o0[4] = {v0.x*scale*w0.x, v0.y*scale*w0.y, v0.z*scale*w0.z, v0.w*scale*w0.w};
    float o1[4] = {v1.x*scale*w1.x, v1.y*scale*w1.y, v1.z*scale*w1.z, v1.w*scale*w1.w};
    #pragma unroll
    for (int p = 0; p < 2; p++) {
        __half h0 = __float2half_rn(o0[p*2]), h1 = __float2half_rn(o0[p*2+1]);
        oh[t*2 + p] = __halves2half2(h0, h1);
        ol[t*2 + p] = __halves2half2(__float2half_rn(o0[p*2]   - __half2float(h0)),
                                     __float2half_rn(o0[p*2+1] - __half2float(h1)));
        __half g0 = __float2half_rn(o1[p*2]), g1 = __float2half_rn(o1[p*2+1]);
        oh[(t+256)*2 + p] = __halves2half2(g0, g1);
        ol[(t+256)*2 + p] = __halves2half2(__float2half_rn(o1[p*2]   - __half2float(g0)),
                                           __float2half_rn(o1[p*2+1] - __half2float(g1)));
    }
}

// ---------------- split-K reduces -------------------------------------------------
__global__ void reduce_split_f32(const float* __restrict__ p, float* __restrict__ o, int n) {
    int i = blockIdx.x * blockDim.x + threadIdx.x;
    if (i >= n) return;
    float s = p[i] + p[i + (size_t)n] + p[i + 2*(size_t)n] + p[i + 3*(size_t)n];
    o[i] = s;
}
__global__ void reduce_split_h2(const float* __restrict__ p,
                                __half* __restrict__ oh, __half* __restrict__ ol, int n) {
    int i = blockIdx.x * blockDim.x + threadIdx.x;
    if (i >= n) return;
    float s = p[i] + p[i + (size_t)n] + p[i + 2*(size_t)n] + p[i + 3*(size_t)n];
    __half hh = __float2half_rn(s);
    oh[i] = hh;
    ol[i] = __float2half_rn(s - __half2float(hh));
}

// ---------------- depthwise causal conv(K=4) + SiLU ------------------------------
__global__ void conv_silu_kernel(const float* __restrict__ cw, const float* __restrict__ cb) {
    int idx = blockIdx.x * blockDim.x + threadIdx.x;   // < Mm*Ee
    int e = idx & (Ee - 1);
    int l = (idx >> 12) & (Ll - 1);
    float w0 = cw[e * 4 + 0], w1 = cw[e * 4 + 1], w2 = cw[e * 4 + 2], w3 = cw[e * 4 + 3];
    const float* xp = g_xin + idx;
    float acc = cb[e] + w3 * xp[0];
    if (l >= 1) acc += w2 * xp[-Ee];
    if (l >= 2) acc += w1 * xp[-2 * Ee];
    if (l >= 3) acc += w0 * xp[-3 * Ee];
    float v = acc / (1.f + __expf(-acc));
    g_xs[idx] = v;
    __half hh = __float2half_rn(v);
    g_xsh[idx] = hh;
    g_xsl[idx] = __float2half_rn(v - __half2float(hh));
}

// ---------------- pack W_Bm / W_Cm (fp16 hi/lo, rows 32..127 zero) ----------------
__global__ void pack_wbc_kernel(const float* __restrict__ wb, const float* __restrict__ wc) {
    int i = blockIdx.x * blockDim.x + threadIdx.x;     // < 128*Ee
    int row = i >> 12;
    int k = i & (Ee - 1);
    float v = 0.f;
    if (row < 16)      v = wb[row * Ee + k];
    else if (row < 32) v = wc[(row - 16) * Ee + k];
    __half hh = __float2half_rn(v);
    g_wbch[i] = hh;
    g_wbcl[i] = __float2half_rn(v - __half2float(hh));
}

// ---------------- selective scan ---------------------------------------------------
__global__ __launch_bounds__(128)
void scan_kernel(const float* __restrict__ A_log, const float* __restrict__ W_D) {
    const int tid = threadIdx.x;
    const int half = tid >> 4;
    const int n = tid & 15;
    const int ch = blockIdx.x * 8 + half;   // 0..Bb*Ee-1
    const int b = ch >> 12;
    const int e = ch & (Ee - 1);
    const float An = -__expf(A_log[e * Nn + n]);
    const float wD = W_D[e];
    float h = 0.f;
    int base = (b * Ll) * Ee + e;
    int bcb = (b * Ll) * 128 + n;
    for (int l = 0; l < Ll; ++l) {
        float d  = g_delta[base];
        float xv = g_xs[base];
        float bv = g_BC[bcb];
        float cv = g_BC[bcb + 16];
        float a = __expf(d * An);
        h = fmaf(a, h, d * xv * bv);
        float p = h * cv;
        p += __shfl_xor_sync(0xffffffffu, p, 8);
        p += __shfl_xor_sync(0xffffffffu, p, 4);
        p += __shfl_xor_sync(0xffffffffu, p, 2);
        p += __shfl_xor_sync(0xffffffffu, p, 1);
        if (n == 0) {
            float sk = g_skip[base];
            float sg = sk / (1.f + __expf(-sk));
            float yv = (p + xv * wD) * sg;
            __half hh = __float2half_rn(yv);
            g_yh[base] = hh;
            g_yl[base] = __float2half_rn(yv - __half2float(hh));
        }
        base += Ee;
        bcb += 128;
    }
}

// ---------------- host orchestration ----------------------------------------------
extern "C" void kernel_launch(void* const* d_in, const int* in_sizes, int n_in,
                              void* d_out, int out_size) {
    const float* resid  = (const float*)d_in[0];
    const float* norm_w = (const float*)d_in[1];
    const float* W_skip = (const float*)d_in[2];
    const float* W_in   = (const float*)d_in[3];
    const float* conv_w = (const float*)d_in[4];
    const float* conv_b = (const float*)d_in[5];
    const float* W_d1   = (const float*)d_in[6];
    const float* W_d2   = (const float*)d_in[7];
    const float* b_d2   = (const float*)d_in[8];
    const float* W_Bm   = (const float*)d_in[9];
    const float* W_Cm   = (const float*)d_in[10];
    const float* A_log  = (const float*)d_in[11];
    const float* W_D    = (const float*)d_in[12];
    const float* W_out  = (const float*)d_in[13];
    float* out = (float*)d_out;

    // symbol addresses
    float *p_skip, *p_xin, *p_xs, *p_BC, *p_part, *p_delta;
    __half *p_xnh, *p_xnl, *p_xsh, *p_xsl, *p_yh, *p_yl, *p_d1h, *p_d1l;
    __half *p_wskiph, *p_wskipl, *p_winh, *p_winl, *p_wouth, *p_woutl;
    __half *p_wbch, *p_wbcl, *p_wd1h, *p_wd1l, *p_wd2h, *p_wd2l;
    cudaGetSymbolAddress((void**)&p_skip, g_skip);
    cudaGetSymbolAddress((void**)&p_xin, g_xin);
    cudaGetSymbolAddress((void**)&p_xs, g_xs);
    cudaGetSymbolAddress((void**)&p_BC, g_BC);
    cudaGetSymbolAddress((void**)&p_part, g_part);
    cudaGetSymbolAddress((void**)&p_delta, g_delta);
    cudaGetSymbolAddress((void**)&p_xnh, g_xnh);
    cudaGetSymbolAddress((void**)&p_xnl, g_xnl);
    cudaGetSymbolAddress((void**)&p_xsh, g_xsh);
    cudaGetSymbolAddress((void**)&p_xsl, g_xsl);
    cudaGetSymbolAddress((void**)&p_yh, g_yh);
    cudaGetSymbolAddress((void**)&p_yl, g_yl);
    cudaGetSymbolAddress((void**)&p_d1h, g_d1h);
    cudaGetSymbolAddress((void**)&p_d1l, g_d1l);
    cudaGetSymbolAddress((void**)&p_wskiph, g_wskiph);
    cudaGetSymbolAddress((void**)&p_wskipl, g_wskipl);
    cudaGetSymbolAddress((void**)&p_winh, g_winh);
    cudaGetSymbolAddress((void**)&p_winl, g_winl);
    cudaGetSymbolAddress((void**)&p_wouth, g_wouth);
    cudaGetSymbolAddress((void**)&p_woutl, g_woutl);
    cudaGetSymbolAddress((void**)&p_wbch, g_wbch);
    cudaGetSymbolAddress((void**)&p_wbcl, g_wbcl);
    cudaGetSymbolAddress((void**)&p_wd1h, g_wd1h);
    cudaGetSymbolAddress((void**)&p_wd1l, g_wd1l);
    cudaGetSymbolAddress((void**)&p_wd2h, g_wd2h);
    cudaGetSymbolAddress((void**)&p_wd2l, g_wd2l);

    cudaFuncSetAttribute(gemm_hmma, cudaFuncAttributeMaxDynamicSharedMemorySize, SMEM_DYN);

    // 0. weight conversions (fp32 -> fp16 hi/lo)
    cvt_pair_kernel<<<(Ee * Dd + 255) / 256, 256>>>(W_skip, p_wskiph, p_wskipl, Ee * Dd);
    cvt_pair_kernel<<<(Ee * Dd + 255) / 256, 256>>>(W_in, p_winh, p_winl, Ee * Dd);
    cvt_pair_kernel<<<(Dd * Ee + 255) / 256, 256>>>(W_out, p_wouth, p_woutl, Dd * Ee);
    cvt_pair_kernel<<<(Rr * Ee + 255) / 256, 256>>>(W_d1, p_wd1h, p_wd1l, Rr * Ee);
    cvt_pair_kernel<<<(Ee * Rr + 255) / 256, 256>>>(W_d2, p_wd2h, p_wd2l, Ee * Rr);
    pack_wbc_kernel<<<(128 * Ee) / 256, 256>>>(W_Bm, W_Cm);

    // 1. RMSNorm -> xn hi/lo
    rmsnorm_kernel<<<Mm, 256>>>(resid, norm_w);

    // 2. skip = xn @ W_skip^T  [4096 x 4096], K=2048
    gemm_hmma<<<dim3(Ee / 128, Mm / 128, 1), 256, SMEM_DYN>>>(
        p_xnh, p_xnl, p_wskiph, p_wskipl, p_skip, Mm, Ee, Dd, Dd, 0, nullptr, nullptr);
    // 3. xin = xn @ W_in^T
    gemm_hmma<<<dim3(Ee / 128, Mm / 128, 1), 256, SMEM_DYN>>>(
        p_xnh, p_xnl, p_winh, p_winl, p_xin, Mm, Ee, Dd, Dd, 0, nullptr, nullptr);

    // 4. conv + silu -> xs (fp32 + hi/lo)
    conv_silu_kernel<<<(Mm * Ee) / 256, 256>>>(conv_w, conv_b);

    // 5. BC = xs @ Wbc^T  [4096 x 128], K=4096, split-K=4
    gemm_hmma<<<dim3(1, Mm / 128, 4), 256, SMEM_DYN>>>(
        p_xsh, p_xsl, p_wbch, p_wbcl, p_part, Mm, 128, Ee, Ee / 4, 0, nullptr, nullptr);
    reduce_split_f32<<<(Mm * 128) / 256, 256>>>(p_part, p_BC, Mm * 128);

    // 6. d1 = xs @ W_d1^T  [4096 x 128], K=4096, split-K=4 -> hi/lo
    gemm_hmma<<<dim3(1, Mm / 128, 4), 256, SMEM_DYN>>>(
        p_xsh, p_xsl, p_wd1h, p_wd1l, p_part, Mm, Rr, Ee, Ee / 4, 0, nullptr, nullptr);
    reduce_split_h2<<<(Mm * Rr) / 256, 256>>>(p_part, p_d1h, p_d1l, Mm * Rr);

    // 7. delta = softplus(d1 @ W_d2^T + b_d2)  [4096 x 4096], K=128
    gemm_hmma<<<dim3(Ee / 128, Mm / 128, 1), 256, SMEM_DYN>>>(
        p_d1h, p_d1l, p_wd2h, p_wd2l, p_delta, Mm, Ee, Rr, Rr, 1, b_d2, nullptr);

    // 8. selective scan -> y hi/lo (fused +x*W_D and *silu(skip))
    scan_kernel<<<(Bb * Ee) / 8, 128>>>(A_log, W_D);

    // 9. out = resid + y @ W_out^T  [4096 x 2048], K=4096
    gemm_hmma<<<dim3(Dd / 128, Mm / 128, 1), 256, SMEM_DYN>>>(
        p_yh, p_yl, p_wouth, p_woutl, out, Mm, Dd, Ee, Ee, 2, nullptr, resid);

    (void)in_sizes; (void)n_in; (void)out_size;
}

// round 4
// speedup vs baseline: 1.9261x; 1.1450x over previous
#include <cuda_runtime.h>
#include <cuda_fp16.h>
#include <math.h>
#include <stdint.h>

// Problem constants
#define Bb 2
#define Ll 2048
#define Dd 2048
#define Ee 4096
#define Nn 16
#define Rr 128
#define Mm (Bb*Ll)      // 4096 tokens

// ---------------- fp32 scratch ---------------------------------------------------
__device__ float g_skip[Mm*Ee];
__device__ float g_xin[Mm*Ee];
__device__ float g_xs[Mm*Ee];
__device__ float g_BC[Mm*128];
__device__ float g_part[4*Mm*128];
__device__ float g_delta[Mm*Ee];

// ---------------- fp16 hi/lo scratch ---------------------------------------------
__device__ __half g_xnh[Mm*Dd],  g_xnl[Mm*Dd];
__device__ __half g_xsh[Mm*Ee],  g_xsl[Mm*Ee];
__device__ __half g_yh[Mm*Ee],   g_yl[Mm*Ee];
__device__ __half g_d1h[Mm*Rr],  g_d1l[Mm*Rr];
__device__ __half g_wskiph[Ee*Dd], g_wskipl[Ee*Dd];
__device__ __half g_winh[Ee*Dd],   g_winl[Ee*Dd];
__device__ __half g_wouth[Dd*Ee],  g_woutl[Dd*Ee];
__device__ __half g_wbch[128*Ee],  g_wbcl[128*Ee];
__device__ __half g_wd1h[Rr*Ee],   g_wd1l[Rr*Ee];
__device__ __half g_wd2h[Ee*Rr],   g_wd2l[Ee*Rr];

// =============================== PTX helpers ====================================
__device__ __forceinline__ uint32_t smem_u32(const void* p) {
    uint32_t a;
    asm("{ .reg .u64 t; cvta.to.shared.u64 t, %1; cvt.u32.u64 %0, t; }" : "=r"(a) : "l"(p));
    return a;
}
__device__ __forceinline__ void cp16(uint32_t s, const void* g) {
    uint64_t ga;
    asm("cvta.to.global.u64 %0, %1;" : "=l"(ga) : "l"(g));
    asm volatile("cp.async.cg.shared.global [%0], [%1], 16;" :: "r"(s), "l"(ga) : "memory");
}
#define CP_COMMIT() asm volatile("cp.async.commit_group;" ::: "memory")
#define CP_WAIT1()  asm volatile("cp.async.wait_group 1;" ::: "memory")
#define CP_WAIT0()  asm volatile("cp.async.wait_group 0;" ::: "memory")
#define LDSM4(r, addr) \
    asm volatile("ldmatrix.sync.aligned.m8n8.x4.shared.b16 {%0,%1,%2,%3}, [%4];" \
        : "=r"((r)[0]), "=r"((r)[1]), "=r"((r)[2]), "=r"((r)[3]) : "r"(addr))
#define MMA16816(d, a, b0, b1) \
    asm volatile("mma.sync.aligned.m16n8k16.row.col.f32.f16.f16.f32 " \
        "{%0,%1,%2,%3}, {%4,%5,%6,%7}, {%8,%9}, {%0,%1,%2,%3};" \
        : "+f"((d)[0]), "+f"((d)[1]), "+f"((d)[2]), "+f"((d)[3]) \
        : "r"((a)[0]), "r"((a)[1]), "r"((a)[2]), "r"((a)[3]), "r"(b0), "r"(b1))

// SMEM: per stage: Ah(16KB) Al(16KB) Bh(16KB) Bl(16KB) = 64KB. 3 stages = 192KB.
#define STAGES   3
#define TILE_B   16384
#define STAGE_B  (4 * TILE_B)
#define SMEM_DYN (STAGES * STAGE_B)

// swizzled byte offset in a 128row x 64half tile (row stride 128B, 8 chunks of 16B)
__device__ __forceinline__ uint32_t swz(uint32_t row, uint32_t chunk) {
    return row * 128u + ((chunk ^ (row & 7u)) * 16u);
}

// ======================= HMMA GEMM (fp16 x 3 compensated) =======================
// C[M,N] = A[M,K] @ B[N,K]^T with A=Ah+Al, B=Bh+Bl (fp16 hi/lo).
// 128x128 CTA tile, 512 threads = 16 warps (4M x 4N), warp tile 32x32, k-chunk 64.
// epi: 0=plain (split-K partial if gridDim.z>1), 1=softplus(x+bias[n]), 2=x+addend
__global__ __launch_bounds__(512, 1)
void gemm_hmma(const __half* __restrict__ Ah, const __half* __restrict__ Al,
               const __half* __restrict__ Bh, const __half* __restrict__ Bl,
               float* __restrict__ C, int M, int N, int K, int kChunk,
               int epi, const float* __restrict__ bias,
               const float* __restrict__ addend) {
    extern __shared__ char dsm[];
    const uint32_t sb = smem_u32(dsm);
    const int tid = threadIdx.x, wid = tid >> 5, lane = tid & 31;
    const int m0 = blockIdx.y * 128, n0 = blockIdx.x * 128;
    const int k0 = blockIdx.z * kChunk;
    const int C_CH = kChunk / 64;
    const int m0w = (wid & 3) * 32, n0w = (wid >> 2) * 32;

    const __half* Abh = Ah + (size_t)m0 * K + k0;
    const __half* Abl = Al + (size_t)m0 * K + k0;
    const __half* Bbh = Bh + (size_t)n0 * K + k0;
    const __half* Bbl = Bl + (size_t)n0 * K + k0;

    // loader: 512 threads cover 128 rows x 8 chunks(16B) twice
    const uint32_t s0r = (uint32_t)(tid >> 3),        s0c = (uint32_t)(tid & 7);
    const uint32_t s1r = (uint32_t)((tid + 512) >> 3), s1c = s0c;   // (tid+512)&7 == tid&7
    const uint32_t sw0 = swz(s0r, s0c), sw1 = swz(s1r, s1c);

    // prologue: stages 0..STAGES-2
    #pragma unroll
    for (int s = 0; s < STAGES - 1; s++) {
        if (s < C_CH) {
            uint32_t tb = sb + s * STAGE_B;
            size_t g0 = (size_t)s0r * K + (size_t)s * 64 + s0c * 8;
            size_t g1 = (size_t)s1r * K + (size_t)s * 64 + s1c * 8;
            cp16(tb + sw0,              Abh + g0);  cp16(tb + sw1,              Abh + g1);
            cp16(tb + TILE_B + sw0,     Abl + g0);  cp16(tb + TILE_B + sw1,     Abl + g1);
            cp16(tb + 2*TILE_B + sw0,   Bbh + g0);  cp16(tb + 2*TILE_B + sw1,   Bbh + g1);
            cp16(tb + 3*TILE_B + sw0,   Bbl + g0);  cp16(tb + 3*TILE_B + sw1,   Bbl + g1);
        }
        CP_COMMIT();
    }

    float acc[2][4][4];
    #pragma unroll
    for (int i = 0; i < 2; i++)
        #pragma unroll
        for (int j = 0; j < 4; j++)
            #pragma unroll
            for (int q = 0; q < 4; q++) acc[i][j][q] = 0.f;

    const uint32_t chi = (uint32_t)(lane >> 4);
    const uint32_t lr15 = (uint32_t)(lane & 15);

    for (int t = 0; t < C_CH; t++) {
        if (t + STAGES - 1 < C_CH) { CP_WAIT1(); } else { CP_WAIT0(); }
        __syncthreads();
        // issue loads for chunk t+2
        if (t + STAGES - 1 < C_CH) {
            int tc = t + STAGES - 1;
            uint32_t tb = sb + (tc % STAGES) * STAGE_B;
            size_t g0 = (size_t)s0r * K + (size_t)tc * 64 + s0c * 8;
            size_t g1 = (size_t)s1r * K + (size_t)tc * 64 + s1c * 8;
            cp16(tb + sw0,              Abh + g0);  cp16(tb + sw1,              Abh + g1);
            cp16(tb + TILE_B + sw0,     Abl + g0);  cp16(tb + TILE_B + sw1,     Abl + g1);
            cp16(tb + 2*TILE_B + sw0,   Bbh + g0);  cp16(tb + 2*TILE_B + sw1,   Bbh + g1);
            cp16(tb + 3*TILE_B + sw0,   Bbl + g0);  cp16(tb + 3*TILE_B + sw1,   Bbl + g1);
        }
        CP_COMMIT();

        // compute chunk t
        uint32_t tb = sb + (t % STAGES) * STAGE_B;
        #pragma unroll
        for (int ks = 0; ks < 4; ks++) {
            const uint32_t c = (uint32_t)(ks * 2) + chi;
            uint32_t ah[2][4], al[2][4], bh[2][4], bl[2][4];
            #pragma unroll
            for (int mi = 0; mi < 2; mi++) {
                uint32_t r = (uint32_t)(m0w + mi * 16) + lr15;
                uint32_t ad = tb + swz(r, c);
                LDSM4(ah[mi], ad);
                LDSM4(al[mi], ad + TILE_B);
            }
            #pragma unroll
            for (int np = 0; np < 2; np++) {
                uint32_t r = (uint32_t)(n0w + np * 16) + lr15;
                uint32_t ad = tb + 2 * TILE_B + swz(r, c);
                LDSM4(bh[np], ad);
                LDSM4(bl[np], ad + TILE_B);
            }
            #pragma unroll
            for (int mi = 0; mi < 2; mi++)
                #pragma unroll
                for (int np = 0; np < 2; np++) {
                    MMA16816(acc[mi][np*2+0], ah[mi], bh[np][0], bh[np][2]);
                    MMA16816(acc[mi][np*2+1], ah[mi], bh[np][1], bh[np][3]);
                    MMA16816(acc[mi][np*2+0], ah[mi], bl[np][0], bl[np][2]);
                    MMA16816(acc[mi][np*2+1], ah[mi], bl[np][1], bl[np][3]);
                    MMA16816(acc[mi][np*2+0], al[mi], bh[np][0], bh[np][2]);
                    MMA16816(acc[mi][np*2+1], al[mi], bh[np][1], bh[np][3]);
                }
        }
    }

    // epilogue
    float* Cb = C + (gridDim.z > 1 ? (size_t)blockIdx.z * M * N : 0);
    const int gid = lane >> 2, tig = lane & 3;
    #pragma unroll
    for (int mi = 0; mi < 2; mi++) {
        #pragma unroll
        for (int nj = 0; nj < 4; nj++) {
            int col = n0 + n0w + nj * 8 + tig * 2;
            int row = m0 + m0w + mi * 16 + gid;
            float v[4] = {acc[mi][nj][0], acc[mi][nj][1], acc[mi][nj][2], acc[mi][nj][3]};
            if (epi == 1) {
                float z0 = v[0] + bias[col],     z1 = v[1] + bias[col + 1];
                float z2 = v[2] + bias[col],     z3 = v[3] + bias[col + 1];
                v[0] = (z0 > 20.f) ? z0 : log1pf(expf(z0));
                v[1] = (z1 > 20.f) ? z1 : log1pf(expf(z1));
                v[2] = (z2 > 20.f) ? z2 : log1pf(expf(z2));
                v[3] = (z3 > 20.f) ? z3 : log1pf(expf(z3));
            } else if (epi == 2) {
                v[0] += addend[(size_t)row * N + col];
                v[1] += addend[(size_t)row * N + col + 1];
                v[2] += addend[(size_t)(row + 8) * N + col];
                v[3] += addend[(size_t)(row + 8) * N + col + 1];
            }
            *reinterpret_cast<float2*>(Cb + (size_t)row * N + col)       = make_float2(v[0], v[1]);
            *reinterpret_cast<float2*>(Cb + (size_t)(row + 8) * N + col) = make_float2(v[2], v[3]);
        }
    }
}

// ---------------- fp32 -> fp16 hi/lo convert ------------------------------------
__global__ void cvt_pair_kernel(const float* __restrict__ in,
                                __half* __restrict__ h, __half* __restrict__ l, int n) {
    int i = blockIdx.x * 256 + threadIdx.x;
    if (i >= n) return;
    float v = in[i];
    __half hh = __float2half_rn(v);
    h[i] = hh;
    l[i] = __float2half_rn(v - __half2float(hh));
}

// ---------------- RMSNorm (writes fp16 hi/lo) ------------------------------------
__global__ void rmsnorm_kernel(const float* __restrict__ resid,
                               const float* __restrict__ w) {
    const int row = blockIdx.x;
    const int t = threadIdx.x;
    const float4* in = reinterpret_cast<const float4*>(resid + (size_t)row * Dd);
    float4 v0 = in[t];
    float4 v1 = in[t + 256];
    float ss = v0.x*v0.x + v0.y*v0.y + v0.z*v0.z + v0.w*v0.w
             + v1.x*v1.x + v1.y*v1.y + v1.z*v1.z + v1.w*v1.w;
    #pragma unroll
    for (int o = 16; o > 0; o >>= 1) ss += __shfl_xor_sync(0xffffffffu, ss, o);
    __shared__ float red[8];
    if ((t & 31) == 0) red[t >> 5] = ss;
    __syncthreads();
    float tot = red[0] + red[1] + red[2] + red[3] + red[4] + red[5] + red[6] + red[7];
    float scale = rsqrtf(tot * (1.0f / Dd) + 1e-5f);
    const float4* wv = reinterpret_cast<const float4*>(w);
    float4 w0 = wv[t], w1 = wv[t + 256];
    __half2* oh = reinterpret_cast<__half2*>(g_xnh + (size_t)row * Dd);
    __half2* ol = reinterpret_cast<__half2*>(g_xnl + (size_t)row * Dd);
    float o0[4] = {v0.x*scale*w0.x, v0.y*scale*w0.y, v0.z*scale*w0.z, v0.w*scale*w0.w};
    float o1[4] = {v1.x*scale*w1.x, v1.y*scale*w1.y, v1.z*scale*w1.z, v1.w*scale*w1.w};
    #pragma unroll
    for (int p = 0; p < 2; p++) {
        __half h0 = __float2half_rn(o0[p*2]), h1 = __float2half_rn(o0[p*2+1]);
        oh[t*2 + p] = __halves2half2(h0, h1);
        ol[t*2 + p] = __halves2half2(__float2half_rn(o0[p*2]   - __half2float(h0)),
                                     __float2half_rn(o0[p*2+1] - __half2float(h1)));
        __half g0 = __float2half_rn(o1[p*2]), g1 = __float2half_rn(o1[p*2+1]);
        oh[(t+256)*2 + p] = __halves2half2(g0, g1);
        ol[(t+256)*2 + p] = __halves2half2(__float2half_rn(o1[p*2]   - __half2float(g0)),
                                           __float2half_rn(o1[p*2+1] - __half2float(g1)));
    }
}

// ---------------- split-K reduces -------------------------------------------------
__global__ void reduce_split_f32(const float* __restrict__ p, float* __restrict__ o, int n) {
    int i = blockIdx.x * blockDim.x + threadIdx.x;
    if (i >= n) return;
    float s = p[i] + p[i + (size_t)n] + p[i + 2*(size_t)n] + p[i + 3*(size_t)n];
    o[i] = s;
}
__global__ void reduce_split_h2(const float* __restrict__ p,
                                __half* __restrict__ oh, __half* __restrict__ ol, int n) {
    int i = blockIdx.x * blockDim.x + threadIdx.x;
    if (i >= n) return;
    float s = p[i] + p[i + (size_t)n] + p[i + 2*(size_t)n] + p[i + 3*(size_t)n];
    __half hh = __float2half_rn(s);
    oh[i] = hh;
    ol[i] = __float2half_rn(s - __half2float(hh));
}

// ---------------- depthwise causal conv(K=4) + SiLU ------------------------------
__global__ void conv_silu_kernel(const float* __restrict__ cw, const float* __restrict__ cb) {
    int idx = blockIdx.x * blockDim.x + threadIdx.x;   // < Mm*Ee
    int e = idx & (Ee - 1);
    int l = (idx >> 12) & (Ll - 1);
    float w0 = cw[e * 4 + 0], w1 = cw[e * 4 + 1], w2 = cw[e * 4 + 2], w3 = cw[e * 4 + 3];
    const float* xp = g_xin + idx;
    float acc = cb[e] + w3 * xp[0];
    if (l >= 1) acc += w2 * xp[-Ee];
    if (l >= 2) acc += w1 * xp[-2 * Ee];
    if (l >= 3) acc += w0 * xp[-3 * Ee];
    float v = acc / (1.f + __expf(-acc));
    g_xs[idx] = v;
    __half hh = __float2half_rn(v);
    g_xsh[idx] = hh;
    g_xsl[idx] = __float2half_rn(v - __half2float(hh));
}

// ---------------- pack W_Bm / W_Cm (fp16 hi/lo, rows 32..127 zero) ----------------
__global__ void pack_wbc_kernel(const float* __restrict__ wb, const float* __restrict__ wc) {
    int i = blockIdx.x * blockDim.x + threadIdx.x;     // < 128*Ee
    int row = i >> 12;
    int k = i & (Ee - 1);
    float v = 0.f;
    if (row < 16)      v = wb[row * Ee + k];
    else if (row < 32) v = wc[(row - 16) * Ee + k];
    __half hh = __float2half_rn(v);
    g_wbch[i] = hh;
    g_wbcl[i] = __float2half_rn(v - __half2float(hh));
}

// ---------------- selective scan ---------------------------------------------------
__global__ __launch_bounds__(128)
void scan_kernel(const float* __restrict__ A_log, const float* __restrict__ W_D) {
    const int tid = threadIdx.x;
    const int half = tid >> 4;
    const int n = tid & 15;
    const int ch = blockIdx.x * 8 + half;   // 0..Bb*Ee-1
    const int b = ch >> 12;
    const int e = ch & (Ee - 1);
    const float An = -__expf(A_log[e * Nn + n]);
    const float wD = W_D[e];
    float h = 0.f;
    int base = (b * Ll) * Ee + e;
    int bcb = (b * Ll) * 128 + n;
    for (int l = 0; l < Ll; ++l) {
        float d  = g_delta[base];
        float xv = g_xs[base];
        float bv = g_BC[bcb];
        float cv = g_BC[bcb + 16];
        float a = __expf(d * An);
        h = fmaf(a, h, d * xv * bv);
        float p = h * cv;
        p += __shfl_xor_sync(0xffffffffu, p, 8);
        p += __shfl_xor_sync(0xffffffffu, p, 4);
        p += __shfl_xor_sync(0xffffffffu, p, 2);
        p += __shfl_xor_sync(0xffffffffu, p, 1);
        if (n == 0) {
            float sk = g_skip[base];
            float sg = sk / (1.f + __expf(-sk));
            float yv = (p + xv * wD) * sg;
            __half hh = __float2half_rn(yv);
            g_yh[base] = hh;
            g_yl[base] = __float2half_rn(yv - __half2float(hh));
        }
        base += Ee;
        bcb += 128;
    }
}

// ---------------- host orchestration ----------------------------------------------
extern "C" void kernel_launch(void* const* d_in, const int* in_sizes, int n_in,
                              void* d_out, int out_size) {
    const float* resid  = (const float*)d_in[0];
    const float* norm_w = (const float*)d_in[1];
    const float* W_skip = (const float*)d_in[2];
    const float* W_in   = (const float*)d_in[3];
    const float* conv_w = (const float*)d_in[4];
    const float* conv_b = (const float*)d_in[5];
    const float* W_d1   = (const float*)d_in[6];
    const float* W_d2   = (const float*)d_in[7];
    const float* b_d2   = (const float*)d_in[8];
    const float* W_Bm   = (const float*)d_in[9];
    const float* W_Cm   = (const float*)d_in[10];
    const float* A_log  = (const float*)d_in[11];
    const float* W_D    = (const float*)d_in[12];
    const float* W_out  = (const float*)d_in[13];
    float* out = (float*)d_out;

    // symbol addresses
    float *p_skip, *p_xin, *p_xs, *p_BC, *p_part, *p_delta;
    __half *p_xnh, *p_xnl, *p_xsh, *p_xsl, *p_yh, *p_yl, *p_d1h, *p_d1l;
    __half *p_wskiph, *p_wskipl, *p_winh, *p_winl, *p_wouth, *p_woutl;
    __half *p_wbch, *p_wbcl, *p_wd1h, *p_wd1l, *p_wd2h, *p_wd2l;
    cudaGetSymbolAddress((void**)&p_skip, g_skip);
    cudaGetSymbolAddress((void**)&p_xin, g_xin);
    cudaGetSymbolAddress((void**)&p_xs, g_xs);
    cudaGetSymbolAddress((void**)&p_BC, g_BC);
    cudaGetSymbolAddress((void**)&p_part, g_part);
    cudaGetSymbolAddress((void**)&p_delta, g_delta);
    cudaGetSymbolAddress((void**)&p_xnh, g_xnh);
    cudaGetSymbolAddress((void**)&p_xnl, g_xnl);
    cudaGetSymbolAddress((void**)&p_xsh, g_xsh);
    cudaGetSymbolAddress((void**)&p_xsl, g_xsl);
    cudaGetSymbolAddress((void**)&p_yh, g_yh);
    cudaGetSymbolAddress((void**)&p_yl, g_yl);
    cudaGetSymbolAddress((void**)&p_d1h, g_d1h);
    cudaGetSymbolAddress((void**)&p_d1l, g_d1l);
    cudaGetSymbolAddress((void**)&p_wskiph, g_wskiph);
    cudaGetSymbolAddress((void**)&p_wskipl, g_wskipl);
    cudaGetSymbolAddress((void**)&p_winh, g_winh);
    cudaGetSymbolAddress((void**)&p_winl, g_winl);
    cudaGetSymbolAddress((void**)&p_wouth, g_wouth);
    cudaGetSymbolAddress((void**)&p_woutl, g_woutl);
    cudaGetSymbolAddress((void**)&p_wbch, g_wbch);
    cudaGetSymbolAddress((void**)&p_wbcl, g_wbcl);
    cudaGetSymbolAddress((void**)&p_wd1h, g_wd1h);
    cudaGetSymbolAddress((void**)&p_wd1l, g_wd1l);
    cudaGetSymbolAddress((void**)&p_wd2h, g_wd2h);
    cudaGetSymbolAddress((void**)&p_wd2l, g_wd2l);

    cudaFuncSetAttribute(gemm_hmma, cudaFuncAttributeMaxDynamicSharedMemorySize, SMEM_DYN);

    // 0. weight conversions (fp32 -> fp16 hi/lo)
    cvt_pair_kernel<<<(Ee * Dd + 255) / 256, 256>>>(W_skip, p_wskiph, p_wskipl, Ee * Dd);
    cvt_pair_kernel<<<(Ee * Dd + 255) / 256, 256>>>(W_in, p_winh, p_winl, Ee * Dd);
    cvt_pair_kernel<<<(Dd * Ee + 255) / 256, 256>>>(W_out, p_wouth, p_woutl, Dd * Ee);
    cvt_pair_kernel<<<(Rr * Ee + 255) / 256, 256>>>(W_d1, p_wd1h, p_wd1l, Rr * Ee);
    cvt_pair_kernel<<<(Ee * Rr + 255) / 256, 256>>>(W_d2, p_wd2h, p_wd2l, Ee * Rr);
    pack_wbc_kernel<<<(128 * Ee) / 256, 256>>>(W_Bm, W_Cm);

    // 1. RMSNorm -> xn hi/lo
    rmsnorm_kernel<<<Mm, 256>>>(resid, norm_w);

    // 2. skip = xn @ W_skip^T  [4096 x 4096], K=2048
    gemm_hmma<<<dim3(Ee / 128, Mm / 128, 1), 512, SMEM_DYN>>>(
        p_xnh, p_xnl, p_wskiph, p_wskipl, p_skip, Mm, Ee, Dd, Dd, 0, nullptr, nullptr);
    // 3. xin = xn @ W_in^T
    gemm_hmma<<<dim3(Ee / 128, Mm / 128, 1), 512, SMEM_DYN>>>(
        p_xnh, p_xnl, p_winh, p_winl, p_xin, Mm, Ee, Dd, Dd, 0, nullptr, nullptr);

    // 4. conv + silu -> xs (fp32 + hi/lo)
    conv_silu_kernel<<<(Mm * Ee) / 256, 256>>>(conv_w, conv_b);

    // 5. BC = xs @ Wbc^T  [4096 x 128], K=4096, split-K=4
    gemm_hmma<<<dim3(1, Mm / 128, 4), 512, SMEM_DYN>>>(
        p_xsh, p_xsl, p_wbch, p_wbcl, p_part, Mm, 128, Ee, Ee / 4, 0, nullptr, nullptr);
    reduce_split_f32<<<(Mm * 128) / 256, 256>>>(p_part, p_BC, Mm * 128);

    // 6. d1 = xs @ W_d1^T  [4096 x 128], K=4096, split-K=4 -> hi/lo
    gemm_hmma<<<dim3(1, Mm / 128, 4), 512, SMEM_DYN>>>(
        p_xsh, p_xsl, p_wd1h, p_wd1l, p_part, Mm, Rr, Ee, Ee / 4, 0, nullptr, nullptr);
    reduce_split_h2<<<(Mm * Rr) / 256, 256>>>(p_part, p_d1h, p_d1l, Mm * Rr);

    // 7. delta = softplus(d1 @ W_d2^T + b_d2)  [4096 x 4096], K=128
    gemm_hmma<<<dim3(Ee / 128, Mm / 128, 1), 512, SMEM_DYN>>>(
        p_d1h, p_d1l, p_wd2h, p_wd2l, p_delta, Mm, Ee, Rr, Rr, 1, b_d2, nullptr);

    // 8. selective scan -> y hi/lo (fused +x*W_D and *silu(skip))
    scan_kernel<<<(Bb * Ee) / 8, 128>>>(A_log, W_D);

    // 9. out = resid + y @ W_out^T  [4096 x 2048], K=4096
    gemm_hmma<<<dim3(Dd / 128, Mm / 128, 1), 512, SMEM_DYN>>>(
        p_yh, p_yl, p_wouth, p_woutl, out, Mm, Dd, Ee, Ee, 2, nullptr, resid);

    (void)in_sizes; (void)n_in; (void)out_size;
}